// round 2
// baseline (speedup 1.0000x reference)
#include <cuda_runtime.h>
#include <cuda_bf16.h>
#include <mma.h>

using namespace nvcuda;

#define B_    2
#define S_    2048
#define D_    4096
#define H_    32
#define KVH_  8
#define HD_   128
#define REP_  4
#define SCALE_ 0.08838834764831845f  /* 128^-0.5 */

// ---------------- scratch (device globals; no allocation allowed) ----------
__device__ float g_q  [B_ * S_ * H_   * HD_];   // 64 MB
__device__ float g_k  [B_ * S_ * KVH_ * HD_];   // 16 MB
__device__ float g_v  [B_ * S_ * KVH_ * HD_];   // 16 MB
__device__ float g_att[B_ * S_ * H_   * HD_];   // 64 MB (tf32-rounded by flash)
// tf32-rounded copies of GEMM inputs (removes in-fragment converts)
__device__ float g_xr [B_ * S_ * D_];           // 64 MB
__device__ float g_wqr[D_ * H_ * HD_];          // 64 MB
__device__ float g_wkr[D_ * KVH_ * HD_];        // 16 MB
__device__ float g_wvr[D_ * KVH_ * HD_];        // 16 MB
__device__ float g_wor[H_ * HD_ * D_];          // 64 MB

// ---------------- tf32 pre-rounding (one fused elementwise pass) -----------
// float4 segment sizes
#define XF4   4194304u   /* 16.7M floats /4 */
#define WQF4  4194304u
#define WKF4  1048576u
#define WVF4  1048576u
#define WOF4  4194304u
#define TOTF4 (XF4 + WQF4 + WKF4 + WVF4 + WOF4)   /* 14,680,064 */

__device__ __forceinline__ float4 round4(float4 v) {
    v.x = wmma::__float_to_tf32(v.x);
    v.y = wmma::__float_to_tf32(v.y);
    v.z = wmma::__float_to_tf32(v.z);
    v.w = wmma::__float_to_tf32(v.w);
    return v;
}

__global__ __launch_bounds__(256) void round_all(
    const float* __restrict__ x,  const float* __restrict__ wq,
    const float* __restrict__ wk, const float* __restrict__ wv,
    const float* __restrict__ wo,
    float* __restrict__ xr, float* __restrict__ wqr, float* __restrict__ wkr,
    float* __restrict__ wvr, float* __restrict__ wor)
{
    unsigned i = blockIdx.x * blockDim.x + threadIdx.x;
    if (i >= TOTF4) return;
    const float4* src; float4* dst; unsigned off;
    if (i < XF4)                        { src = (const float4*)x;  dst = (float4*)xr;  off = i; }
    else if (i < XF4 + WQF4)            { src = (const float4*)wq; dst = (float4*)wqr; off = i - XF4; }
    else if (i < XF4 + WQF4 + WKF4)     { src = (const float4*)wk; dst = (float4*)wkr; off = i - XF4 - WQF4; }
    else if (i < XF4 + WQF4 + WKF4 + WVF4)
                                        { src = (const float4*)wv; dst = (float4*)wvr; off = i - XF4 - WQF4 - WKF4; }
    else                                { src = (const float4*)wo; dst = (float4*)wor; off = i - XF4 - WQF4 - WKF4 - WVF4; }
    dst[off] = round4(src[off]);
}

// ---------------- pipelined tf32 WMMA GEMM:  C = A @ W ---------------------
#define BM 128
#define BN 128
#define BK 32
#define STAGES  3
#define A_PITCH 36                 // floats (144 B rows, 16B-aligned)
#define B_PITCH 132                // floats (528 B rows, 16B-aligned)
#define A_STAGE (BM * A_PITCH)     // 4608 floats
#define B_STAGE (BK * B_PITCH)     // 4224 floats
#define GEMM_SMEM_BYTES (STAGES * (A_STAGE + B_STAGE) * 4)   // 105,984 B

__device__ __forceinline__ void cp_async16(void* smem_dst, const void* gsrc) {
    unsigned saddr = (unsigned)__cvta_generic_to_shared(smem_dst);
    asm volatile("cp.async.cg.shared.global [%0], [%1], 16;\n"
                 :: "r"(saddr), "l"(gsrc));
}

__global__ __launch_bounds__(256, 2) void gemm_tf32(
    const float* __restrict__ A, const float* __restrict__ W,
    float* __restrict__ C, int M, int N, int K)
{
    extern __shared__ float sm[];
    float* As = sm;
    float* Bs = sm + STAGES * A_STAGE;

    const int tid  = threadIdx.x;
    const int warp = tid >> 5;
    const int wm   = warp >> 2;    // 0..1
    const int wn   = warp & 3;     // 0..3
    const int tm   = blockIdx.y * BM;
    const int tn   = blockIdx.x * BN;

    const int ar = tid >> 3;              // +i*32 -> 0..127
    const int ac = (tid & 7) * 4;
    const int br = tid >> 5;              // +i*8  -> 0..31
    const int bc = (tid & 31) * 4;

    auto load_stage = [&](int t, int stg) {
        const float* Ab = A + (size_t)tm * K + t * BK;
        const float* Wb = W + (size_t)t * BK * N + tn;
        float* as = As + stg * A_STAGE;
        float* bs = Bs + stg * B_STAGE;
#pragma unroll
        for (int i = 0; i < 4; i++)
            cp_async16(as + (ar + i * 32) * A_PITCH + ac,
                       Ab + (size_t)(ar + i * 32) * K + ac);
#pragma unroll
        for (int i = 0; i < 4; i++)
            cp_async16(bs + (br + i * 8) * B_PITCH + bc,
                       Wb + (size_t)(br + i * 8) * N + bc);
    };

    wmma::fragment<wmma::accumulator, 16, 16, 8, float> acc[4][2];
#pragma unroll
    for (int i = 0; i < 4; i++)
#pragma unroll
        for (int j = 0; j < 2; j++) wmma::fill_fragment(acc[i][j], 0.0f);

    const int T = K / BK;

#pragma unroll
    for (int t = 0; t < STAGES - 1; t++) {
        load_stage(t, t);
        asm volatile("cp.async.commit_group;\n" ::);
    }

    for (int kt = 0; kt < T; kt++) {
        int pf = kt + STAGES - 1;
        if (pf < T) load_stage(pf, pf % STAGES);
        asm volatile("cp.async.commit_group;\n" ::);
        asm volatile("cp.async.wait_group %0;\n" :: "n"(STAGES - 2));
        __syncthreads();

        const int stg = kt % STAGES;
        const float* as = As + stg * A_STAGE;
        const float* bs = Bs + stg * B_STAGE;
#pragma unroll
        for (int kk = 0; kk < 4; kk++) {
            wmma::fragment<wmma::matrix_a, 16, 16, 8, wmma::precision::tf32,
                           wmma::row_major> a[4];
            wmma::fragment<wmma::matrix_b, 16, 16, 8, wmma::precision::tf32,
                           wmma::row_major> b[2];
#pragma unroll
            for (int i = 0; i < 4; i++)
                wmma::load_matrix_sync(a[i],
                    as + (wm * 64 + i * 16) * A_PITCH + kk * 8, A_PITCH);
#pragma unroll
            for (int j = 0; j < 2; j++)
                wmma::load_matrix_sync(b[j],
                    bs + (kk * 8) * B_PITCH + wn * 32 + j * 16, B_PITCH);
#pragma unroll
            for (int i = 0; i < 4; i++)
#pragma unroll
                for (int j = 0; j < 2; j++)
                    wmma::mma_sync(acc[i][j], a[i], b[j], acc[i][j]);
        }
        __syncthreads();
    }

#pragma unroll
    for (int i = 0; i < 4; i++)
#pragma unroll
        for (int j = 0; j < 2; j++)
            wmma::store_matrix_sync(
                &C[(size_t)(tm + wm * 64 + i * 16) * N + tn + wn * 32 + j * 16],
                acc[i][j], N, wmma::mem_row_major);
}

// ---------------- fused RoPE (q + k in one launch) -------------------------
#define QPAIRS (B_ * S_ * H_   * (HD_ / 2))   /* 8,388,608 */
#define KPAIRS (B_ * S_ * KVH_ * (HD_ / 2))   /* 2,097,152 */

__global__ __launch_bounds__(256) void rope_fused(
    float* __restrict__ q, float* __restrict__ k,
    const float* __restrict__ fc, const float* __restrict__ fs)
{
    int idx = blockIdx.x * blockDim.x + threadIdx.x;
    float* t; int j, heads;
    if (idx < QPAIRS)                { t = q; j = idx;          heads = H_; }
    else if (idx < QPAIRS + KPAIRS)  { t = k; j = idx - QPAIRS; heads = KVH_; }
    else return;
    int pair = j & 63;
    int s    = (j / (64 * heads)) % S_;
    float2 v = reinterpret_cast<float2*>(t)[j];
    float c  = fc[s * 64 + pair];
    float sn = fs[s * 64 + pair];
    float r = v.x, im = v.y;
    v.x = r * c - im * sn;
    v.y = r * sn + im * c;
    reinterpret_cast<float2*>(t)[j] = v;
}

// ---------------- flash attention (fp32 SIMT, streaming softmax) -----------
__global__ __launch_bounds__(128) void flash_attn(
    const float* __restrict__ q, const float* __restrict__ k,
    const float* __restrict__ v, float* __restrict__ o)
{
    __shared__ float Qs[16][HD_];
    __shared__ float Kt[HD_][33];
    __shared__ float Vs[32][HD_];

    const int tid  = threadIdx.x;
    const int lane = tid & 31;
    const int warp = tid >> 5;
    const int q0   = blockIdx.x * 16;
    const int h    = blockIdx.y;
    const int b    = blockIdx.z;
    const int kvh  = h >> 2;

#pragma unroll
    for (int i = 0; i < 4; i++) {
        int fidx = tid + i * 128;
        int r = fidx >> 5;
        int c = (fidx & 31) * 4;
        *reinterpret_cast<float4*>(&Qs[r][c]) =
            *reinterpret_cast<const float4*>(
                &q[((size_t)(b * S_ + q0 + r) * H_ + h) * HD_ + c]);
    }

    float o_acc[4][4];
    float m_r[4], l_r[4];
#pragma unroll
    for (int r = 0; r < 4; r++) {
        m_r[r] = -1e30f; l_r[r] = 0.0f;
#pragma unroll
        for (int i = 0; i < 4; i++) o_acc[r][i] = 0.0f;
    }

    const int rbase   = warp * 4;
    const int n_tiles = (q0 + 16 + 31) >> 5;

    for (int t = 0; t < n_tiles; t++) {
        const int key0 = t * 32;
        __syncthreads();
#pragma unroll
        for (int i = 0; i < 32; i++)
            Kt[tid][i] = k[((size_t)(b * S_ + key0 + i) * KVH_ + kvh) * HD_ + tid];
#pragma unroll
        for (int i = 0; i < 8; i++) {
            int fidx = tid + i * 128;
            int key = fidx >> 5;
            int c   = (fidx & 31) * 4;
            *reinterpret_cast<float4*>(&Vs[key][c]) =
                *reinterpret_cast<const float4*>(
                    &v[((size_t)(b * S_ + key0 + key) * KVH_ + kvh) * HD_ + c]);
        }
        __syncthreads();

#pragma unroll
        for (int r = 0; r < 4; r++) {
            const int qi = q0 + rbase + r;
            float acc = 0.0f;
#pragma unroll
            for (int d = 0; d < HD_; d += 4) {
                float4 qv = *reinterpret_cast<const float4*>(&Qs[rbase + r][d]);
                acc += qv.x * Kt[d + 0][lane];
                acc += qv.y * Kt[d + 1][lane];
                acc += qv.z * Kt[d + 2][lane];
                acc += qv.w * Kt[d + 3][lane];
            }
            const int kj = key0 + lane;
            float sc = acc * SCALE_ + ((kj > qi) ? -1e9f : 0.0f);

            float mt = sc;
#pragma unroll
            for (int off = 16; off > 0; off >>= 1)
                mt = fmaxf(mt, __shfl_xor_sync(0xffffffffu, mt, off));
            float mnew = fmaxf(m_r[r], mt);
            float p = __expf(sc - mnew);
            float ps = p;
#pragma unroll
            for (int off = 16; off > 0; off >>= 1)
                ps += __shfl_xor_sync(0xffffffffu, ps, off);
            float corr = __expf(m_r[r] - mnew);
            l_r[r] = l_r[r] * corr + ps;
            m_r[r] = mnew;
#pragma unroll
            for (int i = 0; i < 4; i++) o_acc[r][i] *= corr;

#pragma unroll
            for (int j = 0; j < 32; j++) {
                float pj = __shfl_sync(0xffffffffu, p, j);
                float4 vv = *reinterpret_cast<const float4*>(&Vs[j][lane * 4]);
                o_acc[r][0] += pj * vv.x;
                o_acc[r][1] += pj * vv.y;
                o_acc[r][2] += pj * vv.z;
                o_acc[r][3] += pj * vv.w;
            }
        }
    }

#pragma unroll
    for (int r = 0; r < 4; r++) {
        float inv = 1.0f / l_r[r];
        // tf32-round the attention output: it is the A operand of the out-proj
        float4 out4 = make_float4(
            wmma::__float_to_tf32(o_acc[r][0] * inv),
            wmma::__float_to_tf32(o_acc[r][1] * inv),
            wmma::__float_to_tf32(o_acc[r][2] * inv),
            wmma::__float_to_tf32(o_acc[r][3] * inv));
        *reinterpret_cast<float4*>(
            &o[((size_t)(b * S_ + q0 + rbase + r) * H_ + h) * HD_ + lane * 4]) = out4;
    }
}

// ---------------- entry point ----------------------------------------------
extern "C" void kernel_launch(void* const* d_in, const int* in_sizes, int n_in,
                              void* d_out, int out_size)
{
    const float* x  = (const float*)d_in[0];
    const float* fc = (const float*)d_in[1];
    const float* fs = (const float*)d_in[2];
    const float* wq = (const float*)d_in[4];
    const float* wk = (const float*)d_in[5];
    const float* wv = (const float*)d_in[6];
    const float* wo = (const float*)d_in[7];
    float* out = (float*)d_out;

    float *q, *k, *v, *att, *xr, *wqr, *wkr, *wvr, *wor;
    cudaGetSymbolAddress((void**)&q,   g_q);
    cudaGetSymbolAddress((void**)&k,   g_k);
    cudaGetSymbolAddress((void**)&v,   g_v);
    cudaGetSymbolAddress((void**)&att, g_att);
    cudaGetSymbolAddress((void**)&xr,  g_xr);
    cudaGetSymbolAddress((void**)&wqr, g_wqr);
    cudaGetSymbolAddress((void**)&wkr, g_wkr);
    cudaGetSymbolAddress((void**)&wvr, g_wvr);
    cudaGetSymbolAddress((void**)&wor, g_wor);

    cudaFuncSetAttribute(gemm_tf32,
        cudaFuncAttributeMaxDynamicSharedMemorySize, GEMM_SMEM_BYTES);

    const int M = B_ * S_;   // 4096

    round_all<<<(TOTF4 + 255) / 256, 256>>>(x, wq, wk, wv, wo,
                                            xr, wqr, wkr, wvr, wor);

    gemm_tf32<<<dim3((H_ * HD_) / BN,   M / BM), 256, GEMM_SMEM_BYTES>>>(
        xr, wqr, q, M, H_ * HD_,   D_);
    gemm_tf32<<<dim3((KVH_ * HD_) / BN, M / BM), 256, GEMM_SMEM_BYTES>>>(
        xr, wkr, k, M, KVH_ * HD_, D_);
    gemm_tf32<<<dim3((KVH_ * HD_) / BN, M / BM), 256, GEMM_SMEM_BYTES>>>(
        xr, wvr, v, M, KVH_ * HD_, D_);

    rope_fused<<<(QPAIRS + KPAIRS + 255) / 256, 256>>>(q, k, fc, fs);

    flash_attn<<<dim3(S_ / 16, H_, B_), 128>>>(q, k, v, att);

    gemm_tf32<<<dim3(D_ / BN, M / BM), 256, GEMM_SMEM_BYTES>>>(
        att, wor, out, M, D_, D_);
}

// round 3
// speedup vs baseline: 1.1986x; 1.1986x over previous
#include <cuda_runtime.h>
#include <cuda_bf16.h>
#include <mma.h>

using namespace nvcuda;

#define B_    2
#define S_    2048
#define D_    4096
#define H_    32
#define KVH_  8
#define HD_   128
#define SCALE_ 0.08838834764831845f  /* 128^-0.5 */

// ---------------- scratch (device globals; no allocation allowed) ----------
__device__ float g_q  [B_ * S_ * H_   * HD_];     // 64 MB
__device__ float g_k  [B_ * S_ * KVH_ * HD_];     // 16 MB
__device__ float g_v  [B_ * S_ * KVH_ * HD_];     // 16 MB (tf32-rounded in epilogue)
__device__ float g_att[B_ * S_ * H_   * HD_];     // 64 MB (tf32-rounded in epilogue)
__device__ float g_xr [B_ * S_ * D_];             // 64 MB
__device__ float g_wqr[D_ * H_ * HD_];            // 64 MB
__device__ float g_wkr[D_ * KVH_ * HD_];          // 16 MB
__device__ float g_wvr[D_ * KVH_ * HD_];          // 16 MB
__device__ float g_wor[H_ * HD_ * D_];            // 64 MB
__device__ float g_q2 [B_ * S_ * H_   * 256];     // 128 MB  [hi|lo]
__device__ float g_k2 [B_ * S_ * KVH_ * 256];     // 32 MB   [hi|lo]
__device__ float g_probs[(size_t)B_ * H_ * S_ * S_];  // 1 GB scores/probs

// ---------------- tf32 pre-rounding (one fused elementwise pass) -----------
#define XF4   4194304u
#define WQF4  4194304u
#define WKF4  1048576u
#define WVF4  1048576u
#define WOF4  4194304u
#define TOTF4 (XF4 + WQF4 + WKF4 + WVF4 + WOF4)

__device__ __forceinline__ float4 round4(float4 v) {
    v.x = wmma::__float_to_tf32(v.x);
    v.y = wmma::__float_to_tf32(v.y);
    v.z = wmma::__float_to_tf32(v.z);
    v.w = wmma::__float_to_tf32(v.w);
    return v;
}

__global__ __launch_bounds__(256) void round_all(
    const float* __restrict__ x,  const float* __restrict__ wq,
    const float* __restrict__ wk, const float* __restrict__ wv,
    const float* __restrict__ wo,
    float* __restrict__ xr, float* __restrict__ wqr, float* __restrict__ wkr,
    float* __restrict__ wvr, float* __restrict__ wor)
{
    unsigned i = blockIdx.x * blockDim.x + threadIdx.x;
    if (i >= TOTF4) return;
    const float4* src; float4* dst; unsigned off;
    if (i < XF4)                        { src = (const float4*)x;  dst = (float4*)xr;  off = i; }
    else if (i < XF4 + WQF4)            { src = (const float4*)wq; dst = (float4*)wqr; off = i - XF4; }
    else if (i < XF4 + WQF4 + WKF4)     { src = (const float4*)wk; dst = (float4*)wkr; off = i - XF4 - WQF4; }
    else if (i < XF4 + WQF4 + WKF4 + WVF4)
                                        { src = (const float4*)wv; dst = (float4*)wvr; off = i - XF4 - WQF4 - WKF4; }
    else                                { src = (const float4*)wo; dst = (float4*)wor; off = i - XF4 - WQF4 - WKF4 - WVF4; }
    dst[off] = round4(src[off]);
}

// ---------------- pipelined tf32 WMMA GEMM:  C = A @ W ---------------------
#define BM 128
#define BN 128
#define BK 32
#define STAGES  3
#define A_PITCH 36
#define B_PITCH 132
#define A_STAGE (BM * A_PITCH)
#define B_STAGE (BK * B_PITCH)
#define GEMM_SMEM_BYTES (STAGES * (A_STAGE + B_STAGE) * 4)

__device__ __forceinline__ void cp_async16(void* smem_dst, const void* gsrc) {
    unsigned saddr = (unsigned)__cvta_generic_to_shared(smem_dst);
    asm volatile("cp.async.cg.shared.global [%0], [%1], 16;\n"
                 :: "r"(saddr), "l"(gsrc));
}

__global__ __launch_bounds__(256, 2) void gemm_tf32(
    const float* __restrict__ A, const float* __restrict__ W,
    float* __restrict__ C, int M, int N, int K, int round_out)
{
    extern __shared__ float sm[];
    float* As = sm;
    float* Bs = sm + STAGES * A_STAGE;

    const int tid  = threadIdx.x;
    const int warp = tid >> 5;
    const int wm   = warp >> 2;
    const int wn   = warp & 3;
    const int tm   = blockIdx.y * BM;
    const int tn   = blockIdx.x * BN;

    const int ar = tid >> 3;
    const int ac = (tid & 7) * 4;
    const int br = tid >> 5;
    const int bc = (tid & 31) * 4;

    auto load_stage = [&](int t, int stg) {
        const float* Ab = A + (size_t)tm * K + t * BK;
        const float* Wb = W + (size_t)t * BK * N + tn;
        float* as = As + stg * A_STAGE;
        float* bs = Bs + stg * B_STAGE;
#pragma unroll
        for (int i = 0; i < 4; i++)
            cp_async16(as + (ar + i * 32) * A_PITCH + ac,
                       Ab + (size_t)(ar + i * 32) * K + ac);
#pragma unroll
        for (int i = 0; i < 4; i++)
            cp_async16(bs + (br + i * 8) * B_PITCH + bc,
                       Wb + (size_t)(br + i * 8) * N + bc);
    };

    wmma::fragment<wmma::accumulator, 16, 16, 8, float> acc[4][2];
#pragma unroll
    for (int i = 0; i < 4; i++)
#pragma unroll
        for (int j = 0; j < 2; j++) wmma::fill_fragment(acc[i][j], 0.0f);

    const int T = K / BK;
#pragma unroll
    for (int t = 0; t < STAGES - 1; t++) {
        load_stage(t, t);
        asm volatile("cp.async.commit_group;\n" ::);
    }

    for (int kt = 0; kt < T; kt++) {
        int pf = kt + STAGES - 1;
        if (pf < T) load_stage(pf, pf % STAGES);
        asm volatile("cp.async.commit_group;\n" ::);
        asm volatile("cp.async.wait_group %0;\n" :: "n"(STAGES - 2));
        __syncthreads();

        const int stg = kt % STAGES;
        const float* as = As + stg * A_STAGE;
        const float* bs = Bs + stg * B_STAGE;
#pragma unroll
        for (int kk = 0; kk < 4; kk++) {
            wmma::fragment<wmma::matrix_a, 16, 16, 8, wmma::precision::tf32,
                           wmma::row_major> a[4];
            wmma::fragment<wmma::matrix_b, 16, 16, 8, wmma::precision::tf32,
                           wmma::row_major> b[2];
#pragma unroll
            for (int i = 0; i < 4; i++)
                wmma::load_matrix_sync(a[i],
                    as + (wm * 64 + i * 16) * A_PITCH + kk * 8, A_PITCH);
#pragma unroll
            for (int j = 0; j < 2; j++)
                wmma::load_matrix_sync(b[j],
                    bs + (kk * 8) * B_PITCH + wn * 32 + j * 16, B_PITCH);
#pragma unroll
            for (int i = 0; i < 4; i++)
#pragma unroll
                for (int j = 0; j < 2; j++)
                    wmma::mma_sync(acc[i][j], a[i], b[j], acc[i][j]);
        }
        __syncthreads();
    }

    if (round_out) {
#pragma unroll
        for (int i = 0; i < 4; i++)
#pragma unroll
            for (int j = 0; j < 2; j++)
#pragma unroll
                for (int e = 0; e < acc[i][j].num_elements; e++)
                    acc[i][j].x[e] = wmma::__float_to_tf32(acc[i][j].x[e]);
    }

#pragma unroll
    for (int i = 0; i < 4; i++)
#pragma unroll
        for (int j = 0; j < 2; j++)
            wmma::store_matrix_sync(
                &C[(size_t)(tm + wm * 64 + i * 16) * N + tn + wn * 32 + j * 16],
                acc[i][j], N, wmma::mem_row_major);
}

// ---------------- RoPE + 2xTF32 hi/lo split --------------------------------
#define QPAIRS (B_ * S_ * H_   * (HD_ / 2))
#define KPAIRS (B_ * S_ * KVH_ * (HD_ / 2))

__global__ __launch_bounds__(256) void rope_split(
    const float* __restrict__ q, const float* __restrict__ k,
    const float* __restrict__ fc, const float* __restrict__ fs,
    float* __restrict__ q2, float* __restrict__ k2)
{
    int idx = blockIdx.x * blockDim.x + threadIdx.x;
    const float* src; float* dst; int j, heads;
    if (idx < QPAIRS)               { src = q; dst = q2; j = idx;          heads = H_; }
    else if (idx < QPAIRS + KPAIRS) { src = k; dst = k2; j = idx - QPAIRS; heads = KVH_; }
    else return;
    int pair = j & 63;
    int row  = j >> 6;
    int s    = (row / heads) % S_;
    float2 val = reinterpret_cast<const float2*>(src)[j];
    float c  = fc[s * 64 + pair];
    float sn = fs[s * 64 + pair];
    float re = val.x * c - val.y * sn;
    float im = val.x * sn + val.y * c;
    float re_hi = wmma::__float_to_tf32(re);
    float im_hi = wmma::__float_to_tf32(im);
    float re_lo = wmma::__float_to_tf32(re - re_hi);
    float im_lo = wmma::__float_to_tf32(im - im_hi);
    size_t base = (size_t)row * 256;
    dst[base + 2 * pair]           = re_hi;
    dst[base + 2 * pair + 1]       = im_hi;
    dst[base + 128 + 2 * pair]     = re_lo;
    dst[base + 128 + 2 * pair + 1] = im_lo;
}

// ---------------- QK^T scores: causal-tiled batched GEMM, K=256 (hi|lo) ----
#define SC_STAGES 3
#define SC_TILE   (128 * A_PITCH)                       // 4608 floats
#define SC_SMEM   (SC_STAGES * 2 * SC_TILE * 4)         // 110592 B
#define NTRI      136                                   // 16*17/2 causal tiles

__global__ __launch_bounds__(256, 2) void qk_scores(
    const float* __restrict__ q2, const float* __restrict__ k2,
    float* __restrict__ probs)
{
    extern __shared__ float sm[];
    float* As = sm;
    float* Bs = sm + SC_STAGES * SC_TILE;

    const int idx = blockIdx.x;
    int ti = (int)((sqrtf(8.0f * idx + 1.0f) - 1.0f) * 0.5f);
    while ((ti + 1) * (ti + 2) / 2 <= idx) ti++;
    while (ti * (ti + 1) / 2 > idx) ti--;
    const int tj = idx - ti * (ti + 1) / 2;
    const int q0 = ti * 128;
    const int k0 = tj * 128;

    const int bh  = blockIdx.y;
    const int b   = bh >> 5;
    const int h   = bh & 31;
    const int kvh = h >> 2;

    const float* Abase = q2 + ((size_t)(b * S_ + q0) * H_   + h)   * 256;
    const float* Bbase = k2 + ((size_t)(b * S_ + k0) * KVH_ + kvh) * 256;
    const size_t lda = (size_t)H_ * 256;     // 8192
    const size_t ldb = (size_t)KVH_ * 256;   // 2048

    const int tid  = threadIdx.x;
    const int warp = tid >> 5;
    const int wm   = warp >> 2;
    const int wn   = warp & 3;
    const int lr = tid >> 3;            // +i*32 -> 0..127 (tile row)
    const int lc = (tid & 7) * 4;       // 0..28

    auto load_stage = [&](int t, int stg) {
        float* as = As + stg * SC_TILE;
        float* bs = Bs + stg * SC_TILE;
#pragma unroll
        for (int i = 0; i < 4; i++) {
            int r = lr + i * 32;
            cp_async16(as + r * A_PITCH + lc, Abase + (size_t)r * lda + t * BK + lc);
            cp_async16(bs + r * A_PITCH + lc, Bbase + (size_t)r * ldb + t * BK + lc);
        }
    };

    wmma::fragment<wmma::accumulator, 16, 16, 8, float> acc[4][2];
#pragma unroll
    for (int i = 0; i < 4; i++)
#pragma unroll
        for (int j = 0; j < 2; j++) wmma::fill_fragment(acc[i][j], 0.0f);

    const int T = 256 / BK;   // 8
#pragma unroll
    for (int t = 0; t < SC_STAGES - 1; t++) {
        load_stage(t, t);
        asm volatile("cp.async.commit_group;\n" ::);
    }

    for (int kt = 0; kt < T; kt++) {
        int pf = kt + SC_STAGES - 1;
        if (pf < T) load_stage(pf, pf % SC_STAGES);
        asm volatile("cp.async.commit_group;\n" ::);
        asm volatile("cp.async.wait_group %0;\n" :: "n"(SC_STAGES - 2));
        __syncthreads();

        const int stg = kt % SC_STAGES;
        const float* as = As + stg * SC_TILE;
        const float* bs = Bs + stg * SC_TILE;
#pragma unroll
        for (int kk = 0; kk < 4; kk++) {
            wmma::fragment<wmma::matrix_a, 16, 16, 8, wmma::precision::tf32,
                           wmma::row_major> a[4];
            wmma::fragment<wmma::matrix_b, 16, 16, 8, wmma::precision::tf32,
                           wmma::col_major> bfr[2];
#pragma unroll
            for (int i = 0; i < 4; i++)
                wmma::load_matrix_sync(a[i],
                    as + (wm * 64 + i * 16) * A_PITCH + kk * 8, A_PITCH);
#pragma unroll
            for (int j = 0; j < 2; j++)
                wmma::load_matrix_sync(bfr[j],
                    bs + (wn * 32 + j * 16) * A_PITCH + kk * 8, A_PITCH);
#pragma unroll
            for (int i = 0; i < 4; i++)
#pragma unroll
                for (int j = 0; j < 2; j++)
                    wmma::mma_sync(acc[i][j], a[i], bfr[j], acc[i][j]);
        }
        __syncthreads();
    }

    float* Cbase = probs + ((size_t)bh * S_ + q0) * S_ + k0;
#pragma unroll
    for (int i = 0; i < 4; i++)
#pragma unroll
        for (int j = 0; j < 2; j++) {
#pragma unroll
            for (int e = 0; e < acc[i][j].num_elements; e++)
                acc[i][j].x[e] *= SCALE_;
            wmma::store_matrix_sync(
                Cbase + (size_t)(wm * 64 + i * 16) * S_ + wn * 32 + j * 16,
                acc[i][j], S_, wmma::mem_row_major);
        }
}

// ---------------- row softmax (causal length, in place, tf32-rounded) ------
__global__ __launch_bounds__(128) void softmax_rows(float* __restrict__ probs)
{
    __shared__ float rowbuf[S_];
    __shared__ float red[4], red2[4];

    const int qi = blockIdx.x & (S_ - 1);
    float* row = probs + (size_t)blockIdx.x * S_;
    const int L = qi + 1;
    const int tid  = threadIdx.x;
    const int lane = tid & 31;
    const int warp = tid >> 5;

    float m = -1e30f;
    for (int j = tid; j < L; j += 128) {
        float x = row[j];
        rowbuf[j] = x;
        m = fmaxf(m, x);
    }
#pragma unroll
    for (int off = 16; off > 0; off >>= 1)
        m = fmaxf(m, __shfl_xor_sync(0xffffffffu, m, off));
    if (lane == 0) red[warp] = m;
    __syncthreads();
    m = fmaxf(fmaxf(red[0], red[1]), fmaxf(red[2], red[3]));

    float s = 0.0f;
    for (int j = tid; j < L; j += 128) {
        float e = __expf(rowbuf[j] - m);
        rowbuf[j] = e;
        s += e;
    }
#pragma unroll
    for (int off = 16; off > 0; off >>= 1)
        s += __shfl_xor_sync(0xffffffffu, s, off);
    if (lane == 0) red2[warp] = s;
    __syncthreads();
    s = red2[0] + red2[1] + red2[2] + red2[3];
    const float inv = 1.0f / s;

    for (int j = tid; j < L; j += 128)
        row[j] = wmma::__float_to_tf32(rowbuf[j] * inv);

    const int bound = ((qi >> 7) + 1) << 7;   // pad to the 128-tile edge
    for (int j = L + tid; j < bound; j += 128)
        row[j] = 0.0f;
}

// ---------------- PV: causal batched pipelined GEMM ------------------------
__global__ __launch_bounds__(256, 2) void pv_gemm(
    const float* __restrict__ probs, const float* __restrict__ v,
    float* __restrict__ att)
{
    extern __shared__ float sm[];
    float* As = sm;
    float* Bs = sm + STAGES * A_STAGE;

    const int qt = blockIdx.x;           // 0..15
    const int bh = blockIdx.y;           // 0..63
    const int q0 = qt * 128;
    const int b   = bh >> 5;
    const int h   = bh & 31;
    const int kvh = h >> 2;

    const float* Abase = probs + ((size_t)bh * S_ + q0) * S_;
    const float* Bbase = v + ((size_t)(b * S_) * KVH_ + kvh) * HD_;
    const size_t ldb = (size_t)KVH_ * HD_;   // 1024

    const int tid  = threadIdx.x;
    const int warp = tid >> 5;
    const int wm   = warp >> 2;
    const int wn   = warp & 3;
    const int ar = tid >> 3;
    const int ac = (tid & 7) * 4;
    const int br = tid >> 5;
    const int bc = (tid & 31) * 4;

    auto load_stage = [&](int t, int stg) {
        float* as = As + stg * A_STAGE;
        float* bs = Bs + stg * B_STAGE;
#pragma unroll
        for (int i = 0; i < 4; i++)
            cp_async16(as + (ar + i * 32) * A_PITCH + ac,
                       Abase + (size_t)(ar + i * 32) * S_ + t * BK + ac);
#pragma unroll
        for (int i = 0; i < 4; i++)
            cp_async16(bs + (br + i * 8) * B_PITCH + bc,
                       Bbase + (size_t)(t * BK + br + i * 8) * ldb + bc);
    };

    wmma::fragment<wmma::accumulator, 16, 16, 8, float> acc[4][2];
#pragma unroll
    for (int i = 0; i < 4; i++)
#pragma unroll
        for (int j = 0; j < 2; j++) wmma::fill_fragment(acc[i][j], 0.0f);

    const int T = (qt + 1) * 4;          // causal K: (q0+128)/32 chunks
#pragma unroll
    for (int t = 0; t < STAGES - 1; t++) {
        load_stage(t, t);
        asm volatile("cp.async.commit_group;\n" ::);
    }

    for (int kt = 0; kt < T; kt++) {
        int pf = kt + STAGES - 1;
        if (pf < T) load_stage(pf, pf % STAGES);
        asm volatile("cp.async.commit_group;\n" ::);
        asm volatile("cp.async.wait_group %0;\n" :: "n"(STAGES - 2));
        __syncthreads();

        const int stg = kt % STAGES;
        const float* as = As + stg * A_STAGE;
        const float* bs = Bs + stg * B_STAGE;
#pragma unroll
        for (int kk = 0; kk < 4; kk++) {
            wmma::fragment<wmma::matrix_a, 16, 16, 8, wmma::precision::tf32,
                           wmma::row_major> a[4];
            wmma::fragment<wmma::matrix_b, 16, 16, 8, wmma::precision::tf32,
                           wmma::row_major> bfr[2];
#pragma unroll
            for (int i = 0; i < 4; i++)
                wmma::load_matrix_sync(a[i],
                    as + (wm * 64 + i * 16) * A_PITCH + kk * 8, A_PITCH);
#pragma unroll
            for (int j = 0; j < 2; j++)
                wmma::load_matrix_sync(bfr[j],
                    bs + (kk * 8) * B_PITCH + wn * 32 + j * 16, B_PITCH);
#pragma unroll
            for (int i = 0; i < 4; i++)
#pragma unroll
                for (int j = 0; j < 2; j++)
                    wmma::mma_sync(acc[i][j], a[i], bfr[j], acc[i][j]);
        }
        __syncthreads();
    }

    float* Cbase = att + ((size_t)(b * S_ + q0) * H_ + h) * HD_;
#pragma unroll
    for (int i = 0; i < 4; i++)
#pragma unroll
        for (int j = 0; j < 2; j++) {
#pragma unroll
            for (int e = 0; e < acc[i][j].num_elements; e++)
                acc[i][j].x[e] = wmma::__float_to_tf32(acc[i][j].x[e]);
            wmma::store_matrix_sync(
                Cbase + (size_t)(wm * 64 + i * 16) * (H_ * HD_) + wn * 32 + j * 16,
                acc[i][j], H_ * HD_, wmma::mem_row_major);
        }
}

// ---------------- entry point ----------------------------------------------
extern "C" void kernel_launch(void* const* d_in, const int* in_sizes, int n_in,
                              void* d_out, int out_size)
{
    const float* x  = (const float*)d_in[0];
    const float* fc = (const float*)d_in[1];
    const float* fs = (const float*)d_in[2];
    const float* wq = (const float*)d_in[4];
    const float* wk = (const float*)d_in[5];
    const float* wv = (const float*)d_in[6];
    const float* wo = (const float*)d_in[7];
    float* out = (float*)d_out;

    float *q, *k, *v, *att, *xr, *wqr, *wkr, *wvr, *wor, *q2, *k2, *probs;
    cudaGetSymbolAddress((void**)&q,    g_q);
    cudaGetSymbolAddress((void**)&k,    g_k);
    cudaGetSymbolAddress((void**)&v,    g_v);
    cudaGetSymbolAddress((void**)&att,  g_att);
    cudaGetSymbolAddress((void**)&xr,   g_xr);
    cudaGetSymbolAddress((void**)&wqr,  g_wqr);
    cudaGetSymbolAddress((void**)&wkr,  g_wkr);
    cudaGetSymbolAddress((void**)&wvr,  g_wvr);
    cudaGetSymbolAddress((void**)&wor,  g_wor);
    cudaGetSymbolAddress((void**)&q2,   g_q2);
    cudaGetSymbolAddress((void**)&k2,   g_k2);
    cudaGetSymbolAddress((void**)&probs, g_probs);

    cudaFuncSetAttribute(gemm_tf32,
        cudaFuncAttributeMaxDynamicSharedMemorySize, GEMM_SMEM_BYTES);
    cudaFuncSetAttribute(qk_scores,
        cudaFuncAttributeMaxDynamicSharedMemorySize, SC_SMEM);
    cudaFuncSetAttribute(pv_gemm,
        cudaFuncAttributeMaxDynamicSharedMemorySize, GEMM_SMEM_BYTES);

    const int M = B_ * S_;   // 4096

    round_all<<<(TOTF4 + 255) / 256, 256>>>(x, wq, wk, wv, wo,
                                            xr, wqr, wkr, wvr, wor);

    gemm_tf32<<<dim3((H_ * HD_) / BN,   M / BM), 256, GEMM_SMEM_BYTES>>>(
        xr, wqr, q, M, H_ * HD_,   D_, 0);
    gemm_tf32<<<dim3((KVH_ * HD_) / BN, M / BM), 256, GEMM_SMEM_BYTES>>>(
        xr, wkr, k, M, KVH_ * HD_, D_, 0);
    gemm_tf32<<<dim3((KVH_ * HD_) / BN, M / BM), 256, GEMM_SMEM_BYTES>>>(
        xr, wvr, v, M, KVH_ * HD_, D_, 1);

    rope_split<<<(QPAIRS + KPAIRS + 255) / 256, 256>>>(q, k, fc, fs, q2, k2);

    qk_scores<<<dim3(NTRI, B_ * H_), 256, SC_SMEM>>>(q2, k2, probs);

    softmax_rows<<<B_ * H_ * S_, 128>>>(probs);

    pv_gemm<<<dim3(S_ / 128, B_ * H_), 256, GEMM_SMEM_BYTES>>>(probs, v, att);

    gemm_tf32<<<dim3(D_ / BN, M / BM), 256, GEMM_SMEM_BYTES>>>(
        att, wor, out, M, D_, D_, 0);
}